// round 16
// baseline (speedup 1.0000x reference)
#include <cuda_runtime.h>
#include <cuda_fp16.h>
#include <cstdint>

// ConvTranspose2D via 4 parity-class implicit GEMMs on mma.sync m16n8k16 fp16.
// out[co, 2i+ph, 2j+pw] = b[co] + sum_{ci,a,b} W[co,ci,2a+ph,2b+pw] * x[ci,i-1+a+ph,j-1+b+pw]
// Per class: M=128 (co), N=128 per i-row (j), K=1024 (ci*4 taps). Grid 128x4.
// 4 warps/CTA, warp tile 64x64, fp32 accumulate. R8 structure (proven best)
// with paired-row B layout: LDS.64/STS.64 halves shared-op count on B path.

#define C_IN   256
#define C_OUT  128
#define H_IN   128
#define W_IN   128
#define H_OUT  256
#define K_TOT  1024
#define NCHUNK 32          // 32 k (8 ci) per chunk -> 2 k16-steps
#define XP_H   130
#define XP_W   132
#define XQ     33          // XP_W / 4 quads per row

#define NW_ELEM (4 * NCHUNK * 2048)
#define NW_BLK  (NW_ELEM / 256)                 // 1024
#define NX_QUAD (C_IN * XP_H * XQ)
#define NX_BLK  ((NX_QUAD + 255) / 256)

__device__ __forceinline__ uint32_t pack_half2(float a, float b) {
    uint32_t lo = (uint32_t)__half_as_ushort(__float2half_rn(a));
    uint32_t hi = (uint32_t)__half_as_ushort(__float2half_rn(b));
    return lo | (hi << 16);
}

// A images: per (cls, chunk): [8 mt8][2 ks][32 lane][4 reg] f16x2 words in exact
// m16n8k16 A-fragment order. 1 MB.
__device__ __align__(16) uint32_t g_Wimg[NW_ELEM];
// Overlapping-pair padded fp16 x image: word [ci][r][pc] = (xpad[r][pc-1], xpad[r][pc]).
__device__ __align__(16) uint32_t g_xph[C_IN * XP_H * XP_W];   // 17.6 MB

__global__ void prep_all(const float* __restrict__ Wg, const float* __restrict__ x) {
    if (blockIdx.x < NW_BLK) {
        // ---- weight fragment image ----
        int idx = blockIdx.x * 256 + threadIdx.x;
        int reg   = idx & 3;
        int lane  = (idx >> 2) & 31;
        int ks    = (idx >> 7) & 1;
        int mt8   = (idx >> 8) & 7;
        int chunk = (idx >> 11) & 31;
        int cls   = idx >> 16;
        int ph = cls >> 1, pw = cls & 1;

        int row   = (lane >> 2) + (reg & 1) * 8;       // 0..15
        int co    = mt8 * 16 + row;
        int kcol0 = (lane & 3) * 2 + (reg >> 1) * 8;   // 0..14 even
        int kl32  = ks * 16 + kcol0;
        int ci    = chunk * 8 + (kl32 >> 2);
        int a     = (kcol0 >> 1) & 1;

        const float* wbase = Wg + (co * C_IN + ci) * 16 + (2 * a + ph) * 4 + pw;
        g_Wimg[idx] = pack_half2(wbase[0], wbase[2]);   // (b=0, b=1)
    } else {
        // ---- x pair image, 4 words per thread ----
        int q = (blockIdx.x - NW_BLK) * 256 + threadIdx.x;
        if (q >= NX_QUAD) return;
        int ci  = q / (XP_H * XQ);
        int rem = q % (XP_H * XQ);
        int r   = rem / XQ;
        int pc0 = (rem % XQ) * 4;
        int ih  = r - 1;
        float xv[5];
        const bool rok = (unsigned)ih < (unsigned)H_IN;
        const float* xrow = x + (ci * H_IN + (rok ? ih : 0)) * W_IN;
        #pragma unroll
        for (int m = 0; m < 5; m++) {
            int iw = pc0 - 1 + m;
            xv[m] = (rok && (unsigned)iw < (unsigned)W_IN) ? xrow[iw] : 0.0f;
        }
        uint4 w;
        w.x = pack_half2(xv[0], xv[1]);
        w.y = pack_half2(xv[1], xv[2]);
        w.z = pack_half2(xv[2], xv[3]);
        w.w = pack_half2(xv[3], xv[4]);
        *reinterpret_cast<uint4*>(g_xph + ((size_t)ci * XP_H + r) * XP_W + pc0) = w;
    }
}

__device__ __forceinline__ uint32_t smem_u32(const void* p) {
    uint32_t a;
    asm("{ .reg .u64 t; cvta.to.shared.u64 t, %1; cvt.u32.u64 %0, t; }" : "=r"(a) : "l"(p));
    return a;
}

#define BP64 132   // uint2 (8B) pitch per B row: 132*8B=1056B = 264 banks-words,
                   // 264 % 32 == 8 -> 8-bank shift per row r: conflict-free
                   // for both STS.64 (j-consecutive) and LDS.64 (r x jc tiling).

__global__ __launch_bounds__(128, 2)
void convT_mma(const float* __restrict__ bias, float* __restrict__ out) {
    __shared__ __align__(16) uint32_t Asm[2][2048];    // A frag images, 16 KB
    __shared__ __align__(16) uint2    Bsm[2][8][BP64]; // [buf][ks*4+r][j] paired rows

    const int cls = blockIdx.y;
    const int i   = blockIdx.x;
    const int ph  = cls >> 1, pw = cls & 1;
    const int tid = threadIdx.x;
    const int wid = tid >> 5, lid = tid & 31;
    const int wm  = wid >> 1;     // 0..1 -> co base wm*64
    const int wn  = wid & 1;      // 0..1 -> j  base wn*64

    float acc[4][8][4];
    #pragma unroll
    for (int mt = 0; mt < 4; mt++)
        #pragma unroll
        for (int nt = 0; nt < 8; nt++)
            #pragma unroll
            for (int q = 0; q < 4; q++) acc[mt][nt][q] = 0.0f;

    const uint32_t* Aimg = g_Wimg + (size_t)cls * NCHUNK * 2048;
    const uint32_t sA0 = smem_u32(&Asm[0][0]);
    const uint32_t sA1 = smem_u32(&Asm[1][0]);

    uint32_t bv[16];   // staged B words: [ks*8 + q]

    // A: 8 KB per chunk -> 4 x 16B cp.async per thread (L2-only: .cg).
    #define CPA(c, sbuf)                                                       \
    {                                                                          \
        const uint32_t* src = Aimg + (c) * 2048 + tid * 4;                     \
        uint32_t dst = (sbuf) + tid * 16;                                      \
        _Pragma("unroll")                                                      \
        for (int u = 0; u < 4; u++)                                            \
            asm volatile("cp.async.cg.shared.global [%0], [%1], 16;"           \
                         :: "r"(dst + u * 2048), "l"(src + u * 512));          \
        asm volatile("cp.async.commit_group;");                                \
    }

    // B: thread tid = column j. pair q: ci = c*8 + ks*4 + (q>>1), a = q&1.
    const uint32_t* xb = g_xph + (size_t)(i + ph) * XP_W + tid + pw;
    #define STAGEB(c)                                                          \
    {                                                                          \
        _Pragma("unroll")                                                      \
        for (int ks = 0; ks < 2; ks++)                                         \
            _Pragma("unroll")                                                  \
            for (int q = 0; q < 8; q++) {                                      \
                const int ci = (c) * 8 + ks * 4 + (q >> 1);                    \
                bv[ks * 8 + q] = xb[((size_t)ci * XP_H + (q & 1)) * XP_W];     \
            }                                                                  \
    }

    // NOTE: inner loop var must NOT shadow the pipeline var `p` (macro capture!)
    // Rows q and q+4 stored as one uint2 -> STS.64.
    #define STOREB(buf)                                                        \
    {                                                                          \
        _Pragma("unroll")                                                      \
        for (int ks = 0; ks < 2; ks++)                                         \
            _Pragma("unroll")                                                  \
            for (int q = 0; q < 4; q++)                                        \
                Bsm[buf][ks * 4 + q][tid] =                                    \
                    make_uint2(bv[ks * 8 + q], bv[ks * 8 + q + 4]);            \
    }

    // ---- prologue ----
    CPA(0, sA0);
    STAGEB(0);
    asm volatile("cp.async.wait_group 0;" ::: "memory");
    STOREB(0);
    __syncthreads();

    int p = 0;
    for (int c = 0; c < NCHUNK; c++) {
        if (c + 1 < NCHUNK) {
            CPA(c + 1, p ? sA0 : sA1);   // writes buf p^1 (all warps done reading
            STAGEB(c + 1);               // it: barrier at end of prev iteration)
        }

        const uint32_t* Ab = Asm[p];
        #pragma unroll
        for (int ks = 0; ks < 2; ks++) {
            uint4 af[4];
            #pragma unroll
            for (int mt = 0; mt < 4; mt++)
                af[mt] = reinterpret_cast<const uint4*>(Ab)
                             [((wm * 4 + mt) * 2 + ks) * 32 + lid];
            uint32_t b0[8], b1[8];
            #pragma unroll
            for (int nt = 0; nt < 8; nt++) {
                const int jc = wn * 64 + nt * 8 + (lid >> 2);
                const uint2 w = Bsm[p][ks * 4 + (lid & 3)][jc];   // LDS.64
                b0[nt] = w.x;
                b1[nt] = w.y;
            }
            #pragma unroll
            for (int mt = 0; mt < 4; mt++)
                #pragma unroll
                for (int nt = 0; nt < 8; nt++)
                    asm volatile(
                        "mma.sync.aligned.m16n8k16.row.col.f32.f16.f16.f32 "
                        "{%0,%1,%2,%3}, {%4,%5,%6,%7}, {%8,%9}, {%0,%1,%2,%3};"
                        : "+f"(acc[mt][nt][0]), "+f"(acc[mt][nt][1]),
                          "+f"(acc[mt][nt][2]), "+f"(acc[mt][nt][3])
                        : "r"(af[mt].x), "r"(af[mt].y), "r"(af[mt].z), "r"(af[mt].w),
                          "r"(b0[nt]), "r"(b1[nt]));
        }

        if (c + 1 < NCHUNK) {
            STOREB(p ^ 1);               // safe: compute(c) only read buf p
            asm volatile("cp.async.wait_group 0;" ::: "memory");
            __syncthreads();             // single barrier per chunk
        }
        p ^= 1;
    }

    // ---- epilogue: bias + stride-2 scatter ----
    const int oh = 2 * i + ph;
    #pragma unroll
    for (int mt = 0; mt < 4; mt++) {
        const int co0 = wm * 64 + mt * 16 + (lid >> 2);
        const int co1 = co0 + 8;
        const float bv0 = bias[co0];
        const float bv1 = bias[co1];
        float* r0 = out + ((size_t)co0 * H_OUT + oh) * H_OUT + pw;
        float* r1 = out + ((size_t)co1 * H_OUT + oh) * H_OUT + pw;
        #pragma unroll
        for (int nt = 0; nt < 8; nt++) {
            const int j0 = wn * 64 + nt * 8 + 2 * (lid & 3);
            r0[2 * j0]       = acc[mt][nt][0] + bv0;
            r0[2 * (j0 + 1)] = acc[mt][nt][1] + bv0;
            r1[2 * j0]       = acc[mt][nt][2] + bv1;
            r1[2 * (j0 + 1)] = acc[mt][nt][3] + bv1;
        }
    }
}

extern "C" void kernel_launch(void* const* d_in, const int* in_sizes, int n_in,
                              void* d_out, int out_size) {
    const float* x  = (const float*)d_in[0];   // 256*128*128
    const float* Wg = (const float*)d_in[1];   // 128*256*4*4
    const float* b  = (const float*)d_in[2];   // 128
    float* out = (float*)d_out;                // 128*256*256

    prep_all<<<NW_BLK + NX_BLK, 256>>>(Wg, x);

    dim3 grid(H_IN, 4);
    convT_mma<<<grid, 128>>>(b, out);
}